// round 9
// baseline (speedup 1.0000x reference)
#include <cuda_runtime.h>
#include <cuda_fp16.h>
#include <cstdint>

constexpr int ND = 30000, D = 256, R = 8, KW = 2048;
constexpr int NC     = 72;                    // K chunks of 32 (2304/32)
constexpr int MTILE  = 64;
constexpr int GRID_M = (ND + MTILE - 1) / MTILE;   // 469
constexpr int THREADS = 1024;                 // 32 warps
constexpr int NSB    = 4;                     // B pipeline stages (race-free w/ lookahead 2)

// smem layout (bytes)
constexpr int SINV_OFF = 0;                   // 512 floats = 2048
constexpr int A_OFF    = 2048;
constexpr int A_STAGE  = 64 * 72;             // 4608
constexpr int B_OFF    = A_OFF + 2 * A_STAGE; // 11264
constexpr int B_STAGE  = 512 * 96;            // 49152 (96B stride: conflict-free LDS.64)
constexpr int H_OFF    = B_OFF + 2 * B_STAGE; // 109568 — H aliases B stages 2,3
constexpr int H_STRIDE = 528;
constexpr int SMEM_T   = B_OFF + NSB * B_STAGE;   // 207872

// device scratch (no allocations allowed)
__device__ float  g_sum[(size_t)ND * KW];          // f32 per-(dst,rel) sums (proven)
__device__ float  g_cnt[ND * R];
__device__ __half g_Bh[(size_t)2 * NC * 256 * 32]; // [L][kc][n][perm k32] fp16
__device__ __half g_r2h[256 * 256];                // root2 transposed [n][k] (UNpermuted)

// ---------------------------------------------------------------------------
__device__ __forceinline__ void mma_f16(float* c, const uint32_t* a,
                                        uint32_t b0, uint32_t b1) {
    asm volatile(
        "mma.sync.aligned.m16n8k16.row.col.f32.f16.f16.f32 "
        "{%0,%1,%2,%3}, {%4,%5,%6,%7}, {%8,%9}, {%0,%1,%2,%3};"
        : "+f"(c[0]), "+f"(c[1]), "+f"(c[2]), "+f"(c[3])
        : "r"(a[0]), "r"(a[1]), "r"(a[2]), "r"(a[3]), "r"(b0), "r"(b1));
}
__device__ __forceinline__ void cp_async16(void* smem_dst, const void* gsrc) {
    uint32_t s = (uint32_t)__cvta_generic_to_shared(smem_dst);
    asm volatile("cp.async.cg.shared.global [%0], [%1], 16;" :: "r"(s), "l"(gsrc));
}
#define CP_COMMIT() asm volatile("cp.async.commit_group;" ::: "memory")
#define CP_WAIT(n)  asm volatile("cp.async.wait_group %0;" :: "n"(n) : "memory")

// ---------------------------------------------------------------------------
// Kernel 0: prep — fp16 weights, fragment-PERMUTED [n][k32] chunks; root2 [n][k].
// Perm within each 16-k group: pos p -> k = 16*(p/16) + 8*((p%4)/2) + 2*((p%16)/4) + (p%2)
// so thread t's uint2 read = halfs {2t,2t+1, 8+2t,8+2t+1} (the m16n8k16 B fragment).
// ---------------------------------------------------------------------------
__global__ void prep_kernel(const float* __restrict__ w1, const float* __restrict__ r1,
                            const float* __restrict__ w2, const float* __restrict__ r2) {
    int gid = blockIdx.x * blockDim.x + threadIdx.x;
    if (gid < 2 * NC * 256 * 4) {
        int L   = gid / (NC * 256 * 4);
        int rem = gid % (NC * 256 * 4);
        int kc  = rem >> 10;
        int n   = (rem >> 2) & 255;
        int c8  = rem & 3;
        __half h8[8];
#pragma unroll
        for (int j = 0; j < 8; j++) {
            int p = c8 * 8 + j;
            int q = p & 15;
            int k = kc * 32 + (p >> 4) * 16 + ((q & 3) >> 1) * 8 + (q >> 2) * 2 + (q & 1);
            float x;
            if (L == 0) x = (k < KW) ? w1[(size_t)k * D + n] : r1[(size_t)(k - KW) * D + n];
            else        x = (k < KW) ? w2[(size_t)k * D + n] : 0.f;
            h8[j] = __float2half_rn(x);
        }
        *(uint4*)(g_Bh + ((size_t)(L * NC + kc) * 256 + n) * 32 + c8 * 8) = *(uint4*)h8;
    }
    if (gid < 256 * 32) {
        int n = gid >> 5, c8 = gid & 31;
        __half h8[8];
#pragma unroll
        for (int j = 0; j < 8; j++)
            h8[j] = __float2half_rn(r2[(size_t)(c8 * 8 + j) * 256 + n]);
        *(uint4*)(g_r2h + (size_t)n * 256 + c8 * 8) = *(uint4*)h8;
    }
}

// ---------------------------------------------------------------------------
// Kernel 1: zero f32 sums + counts
// ---------------------------------------------------------------------------
__global__ void zero_kernel() {
    size_t stride = (size_t)gridDim.x * blockDim.x;
    size_t i = (size_t)blockIdx.x * blockDim.x + threadIdx.x;
    float4 z = make_float4(0.f, 0.f, 0.f, 0.f);
    size_t nsum4 = (size_t)ND * KW / 4;
    for (size_t j = i; j < nsum4; j += stride) ((float4*)g_sum)[j] = z;
    size_t ncnt4 = (size_t)ND * R / 4;
    for (size_t j = i; j < ncnt4; j += stride) ((float4*)g_cnt)[j] = z;
}

// ---------------------------------------------------------------------------
// Kernel 2: f32 scatter-add (one warp per edge)
// ---------------------------------------------------------------------------
__global__ void scatter_kernel(const float* __restrict__ x_src,
                               const void*  __restrict__ ei,
                               const void*  __restrict__ et, int E) {
    int gw   = (blockIdx.x * blockDim.x + threadIdx.x) >> 5;
    int lane = threadIdx.x & 31;
    if (gw >= E) return;

    const int* ei32 = (const int*)ei;
    bool is64 = ((ei32[1] | ei32[3] | ei32[5] | ei32[7]) == 0);

    long long s, d, r;
    if (is64) {
        const long long* p = (const long long*)ei;
        s = p[gw]; d = p[E + gw]; r = ((const long long*)et)[gw];
    } else {
        s = ei32[gw]; d = ei32[E + gw]; r = ((const int*)et)[gw];
    }

    const float4* xr  = (const float4*)(x_src + (size_t)s * D);
    float4*       dst = (float4*)(g_sum + ((size_t)d * R + r) * D);
#pragma unroll
    for (int it = 0; it < 2; it++) {
        float4 v = __ldg(xr + lane + 32 * it);
        asm volatile("red.global.add.v4.f32 [%0], {%1,%2,%3,%4};"
                     :: "l"(dst + lane + 32 * it),
                        "f"(v.x), "f"(v.y), "f"(v.z), "f"(v.w) : "memory");
    }
    if (lane == 0) atomicAdd(&g_cnt[d * R + r], 1.0f);
}

// ---------------------------------------------------------------------------
// Kernel 3: fully-fused fp16 GEMM, 1024 threads (32 warps), warp tile 32x32.
//   warps 0-15: layer1 -> h (relu) in smem; warps 16-31: layer2 (+ h@root2)
// ---------------------------------------------------------------------------
__global__ __launch_bounds__(THREADS, 1)
void fused_all(const float* __restrict__ x_dst,
               const float* __restrict__ b1,
               const float* __restrict__ b2,
               float* __restrict__ out) {
    extern __shared__ char smx[];
    float* s_inv = (float*)(smx + SINV_OFF);

    int tid = threadIdx.x, wid = tid >> 5, lane = tid & 31;
    int g = lane >> 2, t = lane & 3;
    int L = wid >> 4, sub = wid & 15;
    int wm = (sub >> 3) * 32;       // 0 / 32
    int cb = (sub & 7) * 32;        // 0..224
    int row0 = blockIdx.x * MTILE;

    if (tid < 512) {                // MTILE*R == 512
        int rl = tid >> 3, rr = tid & 7, grow = row0 + rl;
        float c = (grow < ND) ? g_cnt[grow * R + rr] : 1.0f;
        s_inv[tid] = 1.0f / fmaxf(c, 1.0f);
    }
    __syncthreads();

    float acc[2][4][4];
#pragma unroll
    for (int mi = 0; mi < 2; mi++)
#pragma unroll
        for (int nj = 0; nj < 4; nj++)
#pragma unroll
            for (int q = 0; q < 4; q++) acc[mi][nj][q] = 0.f;

    float4 av; float asc;
    auto ldA = [&](int kc) {
        if (tid < 512) {
            int rl = tid >> 3, c4 = (tid & 7) << 2;
            int grow = row0 + rl;
            av = make_float4(0.f, 0.f, 0.f, 0.f);
            asc = 0.f;
            if (grow < ND) {
                if (kc < 64) {
                    av  = __ldg((const float4*)(g_sum + (size_t)grow * KW + kc * 32 + c4));
                    asc = s_inv[rl * R + (kc >> 3)];
                } else {
                    av  = __ldg((const float4*)(x_dst + (size_t)grow * D + (kc - 64) * 32 + c4));
                    asc = 1.0f;
                }
            }
        }
    };
    auto stA = [&](int s) {
        if (tid < 512) {
            int rl = tid >> 3, c16 = tid & 7;
            __half h4[4];
            h4[0] = __float2half_rn(av.x * asc);
            h4[1] = __float2half_rn(av.y * asc);
            h4[2] = __float2half_rn(av.z * asc);
            h4[3] = __float2half_rn(av.w * asc);
            *(uint2*)(smx + A_OFF + s * A_STAGE + rl * 72 + c16 * 8) = *(uint2*)h4;
        }
    };
    auto ldB = [&](int kc, int s) {
#pragma unroll
        for (int i = 0; i < 2; i++) {
            int idx = tid + i * 1024;           // 2048 x 16B
            int n5 = idx >> 2, c = idx & 3;
            int Lx = n5 >> 8, n = n5 & 255;
            cp_async16(smx + B_OFF + s * B_STAGE + n5 * 96 + c * 16,
                       g_Bh + ((size_t)(Lx * NC + kc) * 256 + n) * 32 + c * 8);
        }
    };
    auto ldRootB = [&](int c, int s) {
#pragma unroll
        for (int i = 0; i < 2; i++) {
            int idx = tid + i * 1024;           // 2048 x 16B
            int n = idx >> 3, cc = idx & 7;
            cp_async16(smx + B_OFF + s * B_STAGE + n * 144 + cc * 16,
                       g_r2h + (size_t)n * 256 + c * 64 + cc * 8);
        }
    };
    auto compute = [&](int sA, int sB) {
        const char* Ab = smx + A_OFF + sA * A_STAGE;
        const char* Bb = smx + B_OFF + sB * B_STAGE;
#pragma unroll
        for (int ks = 0; ks < 2; ks++) {
            int kb = ks * 16;
            uint32_t a[2][4];
#pragma unroll
            for (int mi = 0; mi < 2; mi++) {
                const char* ar = Ab + (wm + mi * 16 + g) * 72 + kb * 2 + t * 4;
                a[mi][0] = *(const uint32_t*)ar;
                a[mi][1] = *(const uint32_t*)(ar + 8 * 72);
                a[mi][2] = *(const uint32_t*)(ar + 16);
                a[mi][3] = *(const uint32_t*)(ar + 8 * 72 + 16);
            }
#pragma unroll
            for (int nj = 0; nj < 4; nj++) {
                int n5 = L * 256 + cb + nj * 8 + g;
                uint2 bv = *(const uint2*)(Bb + n5 * 96 + ks * 32 + t * 8);
                mma_f16(acc[0][nj], a[0], bv.x, bv.y);
                mma_f16(acc[1][nj], a[1], bv.x, bv.y);
            }
        }
    };

    // ---- main loop: 72 chunks; B 4-stage cp.async (lookahead 2) ----
    ldB(0, 0); CP_COMMIT();
    ldB(1, 1); CP_COMMIT();
    ldA(0); stA(0);

    for (int k = 0; k < NC; k++) {
        int sA = k & 1, sB = k % NSB;
        if (k + 2 < NC) ldB(k + 2, (k + 2) % NSB);
        CP_COMMIT();                 // empty groups pad the tail
        if (k + 1 < NC) ldA(k + 1);  // LDG in flight across barrier + compute
        CP_WAIT(2);                  // B chunk k resident
        __syncthreads();             // A chunk k (stored last iter) visible
        compute(sA, sB);
        if (k + 1 < NC) stA(sA ^ 1); // writes the stage NOT being read
    }
    __syncthreads();

    // ---- root2 prologue + layer1 epilogue (h -> smem fp16, aliases B stages 2/3) ----
    ldRootB(0, 0); CP_COMMIT();
    if (L == 0) {
#pragma unroll
        for (int mi = 0; mi < 2; mi++) {
#pragma unroll
            for (int nj = 0; nj < 4; nj++) {
                int col = cb + nj * 8 + 2 * t;
                float ba = __ldg(&b1[col]), bb = __ldg(&b1[col + 1]);
                __half2 h0 = __floats2half2_rn(fmaxf(acc[mi][nj][0] + ba, 0.f),
                                               fmaxf(acc[mi][nj][1] + bb, 0.f));
                __half2 h1 = __floats2half2_rn(fmaxf(acc[mi][nj][2] + ba, 0.f),
                                               fmaxf(acc[mi][nj][3] + bb, 0.f));
                int r = wm + mi * 16 + g;
                *(__half2*)(smx + H_OFF + r * H_STRIDE + col * 2)       = h0;
                *(__half2*)(smx + H_OFF + (r + 8) * H_STRIDE + col * 2) = h1;
            }
        }
    }
    __syncthreads();

    // ---- root phase: layer2 acc += h @ root2 (4 chunks of K=64, stages 0/1) ----
    for (int c = 0; c < 4; c++) {
        int s = c & 1;
        CP_WAIT(0);
        __syncthreads();
        if (c + 1 < 4) { ldRootB(c + 1, s ^ 1); CP_COMMIT(); }
        if (L == 1) {
            const char* Bb = smx + B_OFF + s * B_STAGE;
#pragma unroll
            for (int ks = 0; ks < 4; ks++) {
                int kb = ks * 16;
                uint32_t a[2][4];
#pragma unroll
                for (int mi = 0; mi < 2; mi++) {
                    const char* ar = smx + H_OFF + (wm + mi * 16 + g) * H_STRIDE
                                     + (c * 64 + kb) * 2 + t * 4;
                    a[mi][0] = *(const uint32_t*)ar;
                    a[mi][1] = *(const uint32_t*)(ar + 8 * H_STRIDE);
                    a[mi][2] = *(const uint32_t*)(ar + 16);
                    a[mi][3] = *(const uint32_t*)(ar + 8 * H_STRIDE + 16);
                }
#pragma unroll
                for (int nj = 0; nj < 4; nj++) {
                    int n = cb + nj * 8 + g;
                    const char* br = Bb + n * 144 + kb * 2 + t * 4;
                    uint32_t b0  = *(const uint32_t*)br;
                    uint32_t b1v = *(const uint32_t*)(br + 16);
                    mma_f16(acc[0][nj], a[0], b0, b1v);
                    mma_f16(acc[1][nj], a[1], b0, b1v);
                }
            }
        }
        __syncthreads();
    }

    // ---- layer2 final store ----
    if (L == 1) {
#pragma unroll
        for (int mi = 0; mi < 2; mi++) {
            int r0g = row0 + wm + mi * 16 + g;
#pragma unroll
            for (int nj = 0; nj < 4; nj++) {
                int col = cb + nj * 8 + 2 * t;
                float ba = __ldg(&b2[col]), bb = __ldg(&b2[col + 1]);
                if (r0g < ND)
                    *(float2*)(out + (size_t)r0g * D + col) =
                        make_float2(acc[mi][nj][0] + ba, acc[mi][nj][1] + bb);
                if (r0g + 8 < ND)
                    *(float2*)(out + (size_t)(r0g + 8) * D + col) =
                        make_float2(acc[mi][nj][2] + ba, acc[mi][nj][3] + bb);
            }
        }
    }
}

// ---------------------------------------------------------------------------
extern "C" void kernel_launch(void* const* d_in, const int* in_sizes, int n_in,
                              void* d_out, int out_size) {
    const float* x_src = (const float*)d_in[0];
    const float* x_dst = (const float*)d_in[1];
    const void*  ei    = d_in[2];
    const void*  et    = d_in[3];
    const float* w1    = (const float*)d_in[4];
    const float* root1 = (const float*)d_in[5];
    const float* b1    = (const float*)d_in[6];
    const float* w2    = (const float*)d_in[7];
    const float* root2 = (const float*)d_in[8];
    const float* b2    = (const float*)d_in[9];
    float* out = (float*)d_out;
    int E = in_sizes[3];

    cudaFuncSetAttribute(fused_all, cudaFuncAttributeMaxDynamicSharedMemorySize, SMEM_T);

    prep_kernel<<<(2 * NC * 256 * 4 + 255) / 256, 256>>>(w1, root1, w2, root2);
    zero_kernel<<<2368, 256>>>();
    scatter_kernel<<<(E + 7) / 8, 256>>>(x_src, ei, et, E);

    fused_all<<<GRID_M, THREADS, SMEM_T>>>(x_dst, b1, b2, out);
}

// round 10
// speedup vs baseline: 1.2310x; 1.2310x over previous
#include <cuda_runtime.h>
#include <cuda_fp16.h>
#include <cstdint>

constexpr int ND = 30000, D = 256, R = 8, KW = 2048;
constexpr int NCH    = 36;                    // K chunks of 64 (2304/64)
constexpr int MTILE  = 64;
constexpr int GRID_M = (ND + MTILE - 1) / MTILE;   // 469
constexpr int THREADS = 512;

// smem layout (bytes). Row strides 144 / 528 are ≡16 (mod 128): conflict-free ldmatrix.
constexpr int SINV_OFF = 0;                   // 512 floats
constexpr int A_OFF    = 2048;
constexpr int A_STAGE  = 64 * 144;            // 9216   (64 rows x 64 halfs, 144B stride)
constexpr int B_OFF    = A_OFF + 2 * A_STAGE; // 20480
constexpr int B_STAGE  = 512 * 144;           // 73728  (512 n-rows x 64 halfs)
constexpr int H_OFF    = B_OFF + 2 * B_STAGE; // 167936
constexpr int H_STRIDE = 528;
constexpr int SMEM_T   = H_OFF + 64 * H_STRIDE;   // 201728

// device scratch (no allocations allowed)
__device__ float  g_sum[(size_t)ND * KW];           // f32 per-(dst,rel) sums (proven)
__device__ float  g_cnt[ND * R];
__device__ __half g_Bh[(size_t)2 * NCH * 256 * 64]; // [L][kc][n][k64] fp16
__device__ __half g_r2h[256 * 256];                 // root2 transposed [n][k]

// ---------------------------------------------------------------------------
__device__ __forceinline__ void mma_f16(float* c, const uint32_t* a,
                                        uint32_t b0, uint32_t b1) {
    asm volatile(
        "mma.sync.aligned.m16n8k16.row.col.f32.f16.f16.f32 "
        "{%0,%1,%2,%3}, {%4,%5,%6,%7}, {%8,%9}, {%0,%1,%2,%3};"
        : "+f"(c[0]), "+f"(c[1]), "+f"(c[2]), "+f"(c[3])
        : "r"(a[0]), "r"(a[1]), "r"(a[2]), "r"(a[3]), "r"(b0), "r"(b1));
}
__device__ __forceinline__ void ldsm_x4(uint32_t* r, uint32_t addr) {
    asm volatile("ldmatrix.sync.aligned.m8n8.x4.shared.b16 {%0,%1,%2,%3}, [%4];"
                 : "=r"(r[0]), "=r"(r[1]), "=r"(r[2]), "=r"(r[3]) : "r"(addr));
}
__device__ __forceinline__ void cp_async16(void* smem_dst, const void* gsrc) {
    uint32_t s = (uint32_t)__cvta_generic_to_shared(smem_dst);
    asm volatile("cp.async.cg.shared.global [%0], [%1], 16;" :: "r"(s), "l"(gsrc));
}
#define CP_COMMIT() asm volatile("cp.async.commit_group;" ::: "memory")
#define CP_WAIT0()  asm volatile("cp.async.wait_group 0;" ::: "memory")

// ---------------------------------------------------------------------------
// Kernel 0: prep — fp16 weights [L][kc64][n][k64]; root2 transposed [n][k]
// ---------------------------------------------------------------------------
__global__ void prep_kernel(const float* __restrict__ w1, const float* __restrict__ r1,
                            const float* __restrict__ w2, const float* __restrict__ r2) {
    int gid = blockIdx.x * blockDim.x + threadIdx.x;
    if (gid < 2 * NCH * 256 * 8) {
        int L   = gid / (NCH * 256 * 8);
        int rem = gid % (NCH * 256 * 8);
        int kc  = rem >> 11;            // /(256*8)
        int n   = (rem >> 3) & 255;
        int c8  = rem & 7;
        __half h8[8];
#pragma unroll
        for (int j = 0; j < 8; j++) {
            int k = kc * 64 + c8 * 8 + j;
            float x;
            if (L == 0) x = (k < KW) ? w1[(size_t)k * D + n] : r1[(size_t)(k - KW) * D + n];
            else        x = (k < KW) ? w2[(size_t)k * D + n] : 0.f;
            h8[j] = __float2half_rn(x);
        }
        *(uint4*)(g_Bh + ((size_t)(L * NCH + kc) * 256 + n) * 64 + c8 * 8) = *(uint4*)h8;
    }
    if (gid < 256 * 32) {
        int n = gid >> 5, c8 = gid & 31;
        __half h8[8];
#pragma unroll
        for (int j = 0; j < 8; j++)
            h8[j] = __float2half_rn(r2[(size_t)(c8 * 8 + j) * 256 + n]);
        *(uint4*)(g_r2h + (size_t)n * 256 + c8 * 8) = *(uint4*)h8;
    }
}

// ---------------------------------------------------------------------------
// Kernel 1: zero f32 sums + counts
// ---------------------------------------------------------------------------
__global__ void zero_kernel() {
    size_t stride = (size_t)gridDim.x * blockDim.x;
    size_t i = (size_t)blockIdx.x * blockDim.x + threadIdx.x;
    float4 z = make_float4(0.f, 0.f, 0.f, 0.f);
    size_t nsum4 = (size_t)ND * KW / 4;
    for (size_t j = i; j < nsum4; j += stride) ((float4*)g_sum)[j] = z;
    size_t ncnt4 = (size_t)ND * R / 4;
    for (size_t j = i; j < ncnt4; j += stride) ((float4*)g_cnt)[j] = z;
}

// ---------------------------------------------------------------------------
// Kernel 2: f32 scatter-add (one warp per edge)
// ---------------------------------------------------------------------------
__global__ void scatter_kernel(const float* __restrict__ x_src,
                               const void*  __restrict__ ei,
                               const void*  __restrict__ et, int E) {
    int gw   = (blockIdx.x * blockDim.x + threadIdx.x) >> 5;
    int lane = threadIdx.x & 31;
    if (gw >= E) return;

    const int* ei32 = (const int*)ei;
    bool is64 = ((ei32[1] | ei32[3] | ei32[5] | ei32[7]) == 0);

    long long s, d, r;
    if (is64) {
        const long long* p = (const long long*)ei;
        s = p[gw]; d = p[E + gw]; r = ((const long long*)et)[gw];
    } else {
        s = ei32[gw]; d = ei32[E + gw]; r = ((const int*)et)[gw];
    }

    const float4* xr  = (const float4*)(x_src + (size_t)s * D);
    float4*       dst = (float4*)(g_sum + ((size_t)d * R + r) * D);
#pragma unroll
    for (int it = 0; it < 2; it++) {
        float4 v = __ldg(xr + lane + 32 * it);
        asm volatile("red.global.add.v4.f32 [%0], {%1,%2,%3,%4};"
                     :: "l"(dst + lane + 32 * it),
                        "f"(v.x), "f"(v.y), "f"(v.z), "f"(v.w) : "memory");
    }
    if (lane == 0) atomicAdd(&g_cnt[d * R + r], 1.0f);
}

// ---------------------------------------------------------------------------
// Kernel 3: fully-fused fp16 GEMM, 512 threads, BK=64, ldmatrix fragments.
//   warps 0-7: layer1 -> h (relu) in smem; warps 8-15: layer2 (+ h@root2)
// ---------------------------------------------------------------------------
__global__ __launch_bounds__(THREADS, 1)
void fused_all(const float* __restrict__ x_dst,
               const float* __restrict__ b1,
               const float* __restrict__ b2,
               float* __restrict__ out) {
    extern __shared__ char smx[];
    float* s_inv = (float*)(smx + SINV_OFF);
    uint32_t smb = (uint32_t)__cvta_generic_to_shared(smx);

    int tid = threadIdx.x, wid = tid >> 5, lane = tid & 31;
    int g = lane >> 2, t = lane & 3;
    int L = wid >> 3, sub = wid & 7;
    int wm = (sub >> 2) * 32;       // 0 / 32
    int cb = (sub & 3) * 64;        // 0 / 64 / 128 / 192
    int row0 = blockIdx.x * MTILE;

    // ldmatrix per-lane offsets (A-style and B-style), strides 144 / 528
    int lr = lane & 7, lh = (lane >> 3) & 1, lc = (lane >> 4) & 1;
    uint32_t a_loff = (uint32_t)((wm + lr + lh * 8) * 144 + lc * 16);
    uint32_t b_loff = (uint32_t)((L * 256 + cb + lr + lc * 8) * 144 + lh * 16);
    uint32_t br_loff = (uint32_t)((cb + lr + lc * 8) * 144 + lh * 16);
    uint32_t h_loff = (uint32_t)((wm + lr + lh * 8) * H_STRIDE + lc * 16);

    {
        int rl = tid >> 3, rr = tid & 7, grow = row0 + rl;  // 512 == MTILE*R
        float c = (grow < ND) ? g_cnt[grow * R + rr] : 1.0f;
        s_inv[tid] = 1.0f / fmaxf(c, 1.0f);
    }
    __syncthreads();

    float acc[2][8][4];
#pragma unroll
    for (int mi = 0; mi < 2; mi++)
#pragma unroll
        for (int nj = 0; nj < 8; nj++)
#pragma unroll
            for (int q = 0; q < 4; q++) acc[mi][nj][q] = 0.f;

    float4 av[2]; float asc;
    auto ldA = [&](int kc) {
        int rl = tid >> 3, c8 = tid & 7;        // row, 8-float group
        int grow = row0 + rl;
        av[0] = make_float4(0.f, 0.f, 0.f, 0.f);
        av[1] = av[0]; asc = 0.f;
        if (grow < ND) {
            if (kc < 32) {
                const float* p = g_sum + (size_t)grow * KW + kc * 64 + c8 * 8;
                av[0] = __ldg((const float4*)p);
                av[1] = __ldg((const float4*)p + 1);
                asc = s_inv[rl * R + (kc >> 2)];
            } else {
                const float* p = x_dst + (size_t)grow * D + (kc - 32) * 64 + c8 * 8;
                av[0] = __ldg((const float4*)p);
                av[1] = __ldg((const float4*)p + 1);
                asc = 1.0f;
            }
        }
    };
    auto stA = [&](int s) {
        int rl = tid >> 3, c8 = tid & 7;
        __half h8[8];
        h8[0] = __float2half_rn(av[0].x * asc);
        h8[1] = __float2half_rn(av[0].y * asc);
        h8[2] = __float2half_rn(av[0].z * asc);
        h8[3] = __float2half_rn(av[0].w * asc);
        h8[4] = __float2half_rn(av[1].x * asc);
        h8[5] = __float2half_rn(av[1].y * asc);
        h8[6] = __float2half_rn(av[1].z * asc);
        h8[7] = __float2half_rn(av[1].w * asc);
        *(uint4*)(smx + A_OFF + s * A_STAGE + rl * 144 + c8 * 16) = *(uint4*)h8;
    };
    auto ldB = [&](int kc, int s) {
#pragma unroll
        for (int i = 0; i < 8; i++) {
            int idx = tid + i * 512;            // 4096 x 16B
            int n5 = idx >> 3, c8 = idx & 7;
            int Lx = n5 >> 8, n = n5 & 255;
            cp_async16(smx + B_OFF + s * B_STAGE + n5 * 144 + c8 * 16,
                       g_Bh + ((size_t)(Lx * NCH + kc) * 256 + n) * 64 + c8 * 8);
        }
    };
    auto ldRootB = [&](int c, int s) {
#pragma unroll
        for (int i = 0; i < 4; i++) {
            int idx = tid + i * 512;            // 2048 x 16B
            int n = idx >> 3, c8 = idx & 7;
            cp_async16(smx + B_OFF + s * B_STAGE + n * 144 + c8 * 16,
                       g_r2h + (size_t)n * 256 + c * 64 + c8 * 8);
        }
    };
    auto compute = [&](int s) {
        uint32_t Ab = smb + A_OFF + s * A_STAGE + a_loff;
        uint32_t Bb = smb + B_OFF + s * B_STAGE + b_loff;
#pragma unroll
        for (int ks = 0; ks < 4; ks++) {
            uint32_t a0[4], a1[4];
            ldsm_x4(a0, Ab + ks * 32);
            ldsm_x4(a1, Ab + 16 * 144 + ks * 32);
#pragma unroll
            for (int p = 0; p < 4; p++) {
                uint32_t b[4];
                ldsm_x4(b, Bb + p * 16 * 144 + ks * 32);
                mma_f16(acc[0][2 * p],     a0, b[0], b[1]);
                mma_f16(acc[0][2 * p + 1], a0, b[2], b[3]);
                mma_f16(acc[1][2 * p],     a1, b[0], b[1]);
                mma_f16(acc[1][2 * p + 1], a1, b[2], b[3]);
            }
        }
    };

    // ---- main loop: 36 chunks of K=64; S=2, round-5-proven sync structure ----
    ldB(0, 0); CP_COMMIT();
    ldA(0); stA(0);
    CP_WAIT0();
    __syncthreads();

    for (int k = 0; k < NCH; k++) {
        int s = k & 1;
        if (k + 1 < NCH) { ldB(k + 1, s ^ 1); CP_COMMIT(); ldA(k + 1); }
        compute(s);
        if (k + 1 < NCH) { CP_WAIT0(); stA(s ^ 1); }
        __syncthreads();
    }

    // ---- root2 prologue + layer1 epilogue (h -> smem fp16) ----
    ldRootB(0, 0); CP_COMMIT();
    if (L == 0) {
#pragma unroll
        for (int mi = 0; mi < 2; mi++) {
#pragma unroll
            for (int nj = 0; nj < 8; nj++) {
                int col = cb + nj * 8 + 2 * t;
                float ba = __ldg(&b1[col]), bb = __ldg(&b1[col + 1]);
                __half2 h0 = __floats2half2_rn(fmaxf(acc[mi][nj][0] + ba, 0.f),
                                               fmaxf(acc[mi][nj][1] + bb, 0.f));
                __half2 h1 = __floats2half2_rn(fmaxf(acc[mi][nj][2] + ba, 0.f),
                                               fmaxf(acc[mi][nj][3] + bb, 0.f));
                int r = wm + mi * 16 + g;
                *(__half2*)(smx + H_OFF + r * H_STRIDE + col * 2)       = h0;
                *(__half2*)(smx + H_OFF + (r + 8) * H_STRIDE + col * 2) = h1;
            }
        }
    }
    __syncthreads();

    // ---- root phase: layer2 acc += h @ root2 (4 chunks of K=64) ----
    for (int c = 0; c < 4; c++) {
        int s = c & 1;
        CP_WAIT0();
        __syncthreads();
        if (c + 1 < 4) { ldRootB(c + 1, s ^ 1); CP_COMMIT(); }
        if (L == 1) {
            uint32_t Hb = smb + H_OFF + h_loff + c * 128;
            uint32_t Bb = smb + B_OFF + s * B_STAGE + br_loff;
#pragma unroll
            for (int ks = 0; ks < 4; ks++) {
                uint32_t a0[4], a1[4];
                ldsm_x4(a0, Hb + ks * 32);
                ldsm_x4(a1, Hb + 16 * H_STRIDE + ks * 32);
#pragma unroll
                for (int p = 0; p < 4; p++) {
                    uint32_t b[4];
                    ldsm_x4(b, Bb + p * 16 * 144 + ks * 32);
                    mma_f16(acc[0][2 * p],     a0, b[0], b[1]);
                    mma_f16(acc[0][2 * p + 1], a0, b[2], b[3]);
                    mma_f16(acc[1][2 * p],     a1, b[0], b[1]);
                    mma_f16(acc[1][2 * p + 1], a1, b[2], b[3]);
                }
            }
        }
        __syncthreads();
    }

    // ---- layer2 final store ----
    if (L == 1) {
#pragma unroll
        for (int mi = 0; mi < 2; mi++) {
            int r0g = row0 + wm + mi * 16 + g;
#pragma unroll
            for (int nj = 0; nj < 8; nj++) {
                int col = cb + nj * 8 + 2 * t;
                float ba = __ldg(&b2[col]), bb = __ldg(&b2[col + 1]);
                if (r0g < ND)
                    *(float2*)(out + (size_t)r0g * D + col) =
                        make_float2(acc[mi][nj][0] + ba, acc[mi][nj][1] + bb);
                if (r0g + 8 < ND)
                    *(float2*)(out + (size_t)(r0g + 8) * D + col) =
                        make_float2(acc[mi][nj][2] + ba, acc[mi][nj][3] + bb);
            }
        }
    }
}

// ---------------------------------------------------------------------------
extern "C" void kernel_launch(void* const* d_in, const int* in_sizes, int n_in,
                              void* d_out, int out_size) {
    const float* x_src = (const float*)d_in[0];
    const float* x_dst = (const float*)d_in[1];
    const void*  ei    = d_in[2];
    const void*  et    = d_in[3];
    const float* w1    = (const float*)d_in[4];
    const float* root1 = (const float*)d_in[5];
    const float* b1    = (const float*)d_in[6];
    const float* w2    = (const float*)d_in[7];
    const float* root2 = (const float*)d_in[8];
    const float* b2    = (const float*)d_in[9];
    float* out = (float*)d_out;
    int E = in_sizes[3];

    cudaFuncSetAttribute(fused_all, cudaFuncAttributeMaxDynamicSharedMemorySize, SMEM_T);

    prep_kernel<<<(2 * NCH * 256 * 8 + 255) / 256, 256>>>(w1, root1, w2, root2);
    zero_kernel<<<2368, 256>>>();
    scatter_kernel<<<(E + 7) / 8, 256>>>(x_src, ei, et, E);

    fused_all<<<GRID_M, THREADS, SMEM_T>>>(x_dst, b1, b2, out);
}